// round 2
// baseline (speedup 1.0000x reference)
#include <cuda_runtime.h>
#include <math.h>

#define NL 4
#define NB 16
#define NN 256
#define NC 16
#define NHID 64
#define INV256F (1.0f/256.0f)
#define INVNORM 0.06454972243679028f   /* 1/sqrt(240) */
#define OW_STRIDE 16842752             /* per-layer stride in d_out (ow + ob) */
#define OB_OFF    16777216             /* offset of ob within a layer chunk */

// ---------------- scratch (device globals; no allocs) ----------------
__device__ float g_terms[100*256];          // 100 siren points x (16c x 16d)
__device__ float g_rsums[NL*NB*NN*NC];      // mean over j  -> [l][b][k][c]
__device__ float g_csums[NL*NB*NN*NC];      // mean over k  -> [l][b][j][c]
__device__ float g_allsums[NB*NC*NL];       // [b][c][l]
__device__ float g_sumsb[NB*NC*NL];         // [b][c][l]
__device__ float g_basew[NL*NB*NC];         // [l][b][d]
__device__ float g_baseb[NL*NB*NC];
__device__ float g_colterm[NL*NB*NN*NC];    // [l][b][j][d] (base folded in)
__device__ float g_rowterm[NL*NB*NN*NC];    // [l][b][k][d]

// point-index helpers into g_terms
// global: t*16 + a*4 + b   (t=0..3)
// diag:   64 + t*4 + i     (t=0..5)
// p1:     88 + t*3 + i     (t=0..1, i=0..2)
// m1:     94 + t*3 + i

__device__ __forceinline__ float f_li(int i){ return -1.0f + (2.0f/3.0f)*i; }
__device__ __forceinline__ float f_ti(int m){ return -1.0f + (2.0f/13.0f)*m; }

// ---------------- zero scratch accumulators ----------------
__global__ void zero_kernel(){
    int id = blockIdx.x*blockDim.x + threadIdx.x;   // 131072 threads
    float4 z = make_float4(0.f,0.f,0.f,0.f);
    if (id < 65536) reinterpret_cast<float4*>(g_csums)[id] = z;
    else            reinterpret_cast<float4*>(g_rsums)[id-65536] = z;
    if (id < NB*NC*NL) g_allsums[id] = 0.f;
}

// ---------------- SIREN: 100 points -> 256 outputs each ----------------
__global__ void siren_kernel(const float* __restrict__ sw0, const float* __restrict__ sb0,
                             const float* __restrict__ sw1, const float* __restrict__ sb1,
                             const float* __restrict__ sw2, const float* __restrict__ sb2,
                             const float* __restrict__ swo, const float* __restrict__ sbo){
    int p = blockIdx.x;
    int t = threadIdx.x;
    float x0, x1, x2;
    if (p < 64){        int tt=p>>4, a=(p>>2)&3, bb=p&3; x0=f_li(a);   x1=f_li(bb);  x2=f_ti(tt); }
    else if (p < 88){   int q=p-64;  int tt=q>>2, i=q&3; x0=f_li(i);   x1=f_li(i);   x2=f_ti(4+tt); }
    else if (p < 94){   int q=p-88;  int tt=q/3,  i=q%3; x0=f_li(i);   x1=f_li(i+1); x2=f_ti(10+tt); }
    else {              int q=p-94;  int tt=q/3,  i=q%3; x0=f_li(i+1); x1=f_li(i);   x2=f_ti(12+tt); }

    __shared__ float h[NHID];
    float v = x0*sw0[t] + x1*sw0[NHID+t] + x2*sw0[2*NHID+t] + sb0[t];
    h[t] = sinf(30.0f * v);
    __syncthreads();

    float a1 = sb1[t];
    #pragma unroll 8
    for (int j=0;j<NHID;j++) a1 = fmaf(h[j], sw1[j*NHID+t], a1);
    a1 = sinf(a1);
    __syncthreads(); h[t] = a1; __syncthreads();

    float a2 = sb2[t];
    #pragma unroll 8
    for (int j=0;j<NHID;j++) a2 = fmaf(h[j], sw2[j*NHID+t], a2);
    a2 = sinf(a2);
    __syncthreads(); h[t] = a2; __syncthreads();

    for (int o=t; o<256; o+=NHID){
        float acc = sbo[o];
        #pragma unroll 8
        for (int j=0;j<NHID;j++) acc = fmaf(h[j], swo[j*256+o], acc);
        g_terms[p*256 + o] = acc * INVNORM;
    }
}

// ---------------- fused reduction over w: rsums, csums, allsums ----------------
// grid: x = 16 (kc 0..3, jh 0..3), y = b, z = l ; 256 threads
// thread: c4 = t&3 (float4 chunk of c), klocal = t>>2 ; k = kc*64 + klocal
__global__ void reduce_kernel(const float* __restrict__ w0, const float* __restrict__ w1,
                              const float* __restrict__ w2, const float* __restrict__ w3){
    int l  = blockIdx.z;
    int b  = blockIdx.y;
    int kc = blockIdx.x & 3;
    int jh = blockIdx.x >> 2;
    const float* w = (l==0)?w0:(l==1)?w1:(l==2)?w2:w3;

    int t    = threadIdx.x;
    int c4   = t & 3;
    int k    = kc*64 + (t>>2);
    int lane = t & 31;

    const float4* wp = reinterpret_cast<const float4*>(w);
    float4 racc = make_float4(0.f,0.f,0.f,0.f);
    int j0 = jh*64;

    #pragma unroll 4
    for (int jj=0; jj<64; jj++){
        int j = j0 + jj;
        float4 v = __ldg(wp + (((b*NN + j)*NN + k)<<2) + c4);
        racc.x += v.x; racc.y += v.y; racc.z += v.z; racc.w += v.w;

        // reduce v over the 8 k-values in this warp (lane bits 2..4)
        float4 s = v;
        #pragma unroll
        for (int m=4; m<32; m<<=1){
            s.x += __shfl_xor_sync(0xffffffffu, s.x, m);
            s.y += __shfl_xor_sync(0xffffffffu, s.y, m);
            s.z += __shfl_xor_sync(0xffffffffu, s.z, m);
            s.w += __shfl_xor_sync(0xffffffffu, s.w, m);
        }
        if (lane < 4){
            float* cb = &g_csums[(((l*NB + b)*NN + j)*NC) + lane*4];
            atomicAdd(cb+0, s.x*INV256F);
            atomicAdd(cb+1, s.y*INV256F);
            atomicAdd(cb+2, s.z*INV256F);
            atomicAdd(cb+3, s.w*INV256F);
        }
    }

    // rsums partial (this block covers 64 of 256 j) -> atomicAdd
    float* rb = &g_rsums[(((l*NB + b)*NN + k)*NC) + c4*4];
    atomicAdd(rb+0, racc.x*INV256F);
    atomicAdd(rb+1, racc.y*INV256F);
    atomicAdd(rb+2, racc.z*INV256F);
    atomicAdd(rb+3, racc.w*INV256F);

    // allsums partial: reduce racc over the warp's 8 k-lanes, add
    float4 r = racc;
    #pragma unroll
    for (int m=4; m<32; m<<=1){
        r.x += __shfl_xor_sync(0xffffffffu, r.x, m);
        r.y += __shfl_xor_sync(0xffffffffu, r.y, m);
        r.z += __shfl_xor_sync(0xffffffffu, r.z, m);
        r.w += __shfl_xor_sync(0xffffffffu, r.w, m);
    }
    if (lane < 4){
        const float sc = INV256F*INV256F;
        int cbase = lane*4;
        atomicAdd(&g_allsums[b*64 + (cbase+0)*4 + l], r.x*sc);
        atomicAdd(&g_allsums[b*64 + (cbase+1)*4 + l], r.y*sc);
        atomicAdd(&g_allsums[b*64 + (cbase+2)*4 + l], r.z*sc);
        atomicAdd(&g_allsums[b*64 + (cbase+3)*4 + l], r.w*sc);
    }
}

// ---------------- sums_b: [b][c][l] = mean_j b_l[b,j,c] ----------------
// 64 blocks (l*16+b), 256 threads: c = t&15, jg = t>>4
__global__ void sumsb_kernel(const float* __restrict__ b0, const float* __restrict__ b1,
                             const float* __restrict__ b2, const float* __restrict__ b3){
    int lb = blockIdx.x;
    int l = lb >> 4, b = lb & 15;
    const float* bl = (l==0)?b0:(l==1)?b1:(l==2)?b2:b3;
    int t = threadIdx.x;
    int c = t & 15, jg = t >> 4;
    float acc = 0.f;
    #pragma unroll 4
    for (int m=0; m<16; m++){
        int j = jg*16 + m;
        acc += __ldg(&bl[(b*NN + j)*NC + c]);
    }
    __shared__ float sh[256];
    sh[t] = acc;
    __syncthreads();
    if (t < 16){
        float s = 0.f;
        #pragma unroll
        for (int g=0; g<16; g++) s += sh[g*16 + t];
        g_sumsb[b*64 + t*4 + l] = s * INV256F;
    }
}

// ---------------- base terms from allsums / sums_b ----------------
// 1 block, 1024 threads: id = (l*16+b)*16+d
__global__ void base_kernel(){
    int id = threadIdx.x;
    int l = id >> 8, b = (id >> 4) & 15, d = id & 15;
    float accw = 0.f, accb = 0.f;
    #pragma unroll
    for (int lp=0; lp<NL; lp++){
        #pragma unroll
        for (int c=0; c<NC; c++){
            float as = g_allsums[b*64 + c*4 + lp];
            float sb = g_sumsb[b*64 + c*4 + lp];
            int e = c*16 + d;
            accw = fmaf(as, g_terms[(     l*4 + lp)*256 + e], accw);
            accw = fmaf(sb, g_terms[(16 + l*4 + lp)*256 + e], accw);
            accb = fmaf(as, g_terms[(32 + l*4 + lp)*256 + e], accb);
            accb = fmaf(sb, g_terms[(48 + l*4 + lp)*256 + e], accb);
        }
    }
    g_basew[id] = accw;
    g_baseb[id] = accb;
}

// ---------------- colterm / rowterm / ob ----------------
// 3072 blocks x 256 threads; gid section: 0=colterm, 1=rowterm, 2=ob
__global__ void colrow_kernel(const float* __restrict__ b0, const float* __restrict__ b1,
                              const float* __restrict__ b2, const float* __restrict__ b3,
                              float* __restrict__ out){
    int gid = blockIdx.x*blockDim.x + threadIdx.x;
    int sec = gid >> 18;            // /262144
    int r   = gid & 262143;
    int l = r >> 16, b = (r >> 12) & 15, x = (r >> 4) & 255, d = r & 15;
    const float* bl = (l==0)?b0:(l==1)?b1:(l==2)?b2:b3;

    if (sec == 0){
        float acc = g_basew[(l*NB + b)*NC + d];
        const float* cs = &g_csums[((l*NB + b)*NN + x)*NC];
        const float* T1 = &g_terms[(68 + l)*256];          // t_w_wcol
        #pragma unroll
        for (int c=0; c<NC; c++) acc = fmaf(cs[c], T1[c*16 + d], acc);
        if (l > 0){
            const float* rs  = &g_rsums[(((l-1)*NB + b)*NN + x)*NC];
            const float* bp  = ((l-1)==0?b0:(l-1)==1?b1:(l-1)==2?b2:b3) + (b*NN + x)*NC;
            const float* Tm0 = &g_terms[(94 + (l-1))*256]; // t_w_wm1
            const float* Tm1 = &g_terms[(97 + (l-1))*256]; // t_w_bm1
            #pragma unroll
            for (int c=0; c<NC; c++){
                acc = fmaf(rs[c], Tm0[c*16 + d], acc);
                acc = fmaf(bp[c], Tm1[c*16 + d], acc);
            }
        }
        g_colterm[r] = acc;
    } else if (sec == 1){
        float acc = 0.f;
        const float* rs = &g_rsums[((l*NB + b)*NN + x)*NC];
        const float* bv = bl + (b*NN + x)*NC;
        const float* T0 = &g_terms[(64 + l)*256];          // t_w_wrow
        const float* T3 = &g_terms[(76 + l)*256];          // t_w_b
        #pragma unroll
        for (int c=0; c<NC; c++){
            acc = fmaf(rs[c], T0[c*16 + d], acc);
            acc = fmaf(bv[c], T3[c*16 + d], acc);
        }
        if (l < 3){
            const float* cs = &g_csums[(((l+1)*NB + b)*NN + x)*NC];
            const float* Tp = &g_terms[(88 + l)*256];      // t_w_wp1
            #pragma unroll
            for (int c=0; c<NC; c++) acc = fmaf(cs[c], Tp[c*16 + d], acc);
        }
        g_rowterm[r] = acc;
    } else {
        float acc = g_baseb[(l*NB + b)*NC + d];
        const float* rs = &g_rsums[((l*NB + b)*NN + x)*NC];
        const float* bv = bl + (b*NN + x)*NC;
        const float* T5 = &g_terms[(84 + l)*256];          // t_bb
        const float* T4 = &g_terms[(80 + l)*256];          // t_b_wcol
        #pragma unroll
        for (int c=0; c<NC; c++){
            acc = fmaf(bv[c], T5[c*16 + d], acc);
            acc = fmaf(rs[c], T4[c*16 + d], acc);
        }
        if (l < 3){
            const float* cs = &g_csums[(((l+1)*NB + b)*NN + x)*NC];
            const float* Tb = &g_terms[(91 + l)*256];      // t_b_wp1
            #pragma unroll
            for (int c=0; c<NC; c++) acc = fmaf(cs[c], Tb[c*16 + d], acc);
        }
        out[(size_t)l*OW_STRIDE + OB_OFF + (b*NN + x)*NC + d] = acc;
    }
}

// ---------------- main output pass: ow = w@T + colterm + rowterm ----------------
// grid (j=256, b=16, 4), 256 threads, thread = k. z is mapped 3..0 for L2 reuse.
__global__ void main_kernel(const float* __restrict__ w0, const float* __restrict__ w1,
                            const float* __restrict__ w2, const float* __restrict__ w3,
                            float* __restrict__ out){
    int l = 3 - blockIdx.z;
    int b = blockIdx.y;
    int j = blockIdx.x;
    int t = threadIdx.x;
    const float* w = (l==0)?w0:(l==1)?w1:(l==2)?w2:w3;

    __shared__ float shT[256];
    __shared__ float shcol[16];
    shT[t] = __ldg(&g_terms[(72 + l)*256 + t]);            // t_w_w[l]
    if (t < 16) shcol[t] = g_colterm[((l*NB + b)*NN + j)*NC + t];
    __syncthreads();

    int k = t;
    const float4* wp = reinterpret_cast<const float4*>(w) + (((b*NN + j)*NN + k)<<2);
    float4 wv0 = __ldg(wp+0), wv1 = __ldg(wp+1), wv2 = __ldg(wp+2), wv3 = __ldg(wp+3);
    float wr[16];
    wr[0]=wv0.x; wr[1]=wv0.y; wr[2]=wv0.z; wr[3]=wv0.w;
    wr[4]=wv1.x; wr[5]=wv1.y; wr[6]=wv1.z; wr[7]=wv1.w;
    wr[8]=wv2.x; wr[9]=wv2.y; wr[10]=wv2.z; wr[11]=wv2.w;
    wr[12]=wv3.x; wr[13]=wv3.y; wr[14]=wv3.z; wr[15]=wv3.w;

    const float4* rp = reinterpret_cast<const float4*>(g_rowterm) + (((l*NB + b)*NN + k)<<2);
    float4 a0 = __ldg(rp+0), a1 = __ldg(rp+1), a2 = __ldg(rp+2), a3 = __ldg(rp+3);
    a0.x += shcol[0];  a0.y += shcol[1];  a0.z += shcol[2];  a0.w += shcol[3];
    a1.x += shcol[4];  a1.y += shcol[5];  a1.z += shcol[6];  a1.w += shcol[7];
    a2.x += shcol[8];  a2.y += shcol[9];  a2.z += shcol[10]; a2.w += shcol[11];
    a3.x += shcol[12]; a3.y += shcol[13]; a3.z += shcol[14]; a3.w += shcol[15];

    #pragma unroll
    for (int c=0; c<16; c++){
        float wc = wr[c];
        const float4* Tp = reinterpret_cast<const float4*>(&shT[c*16]);
        float4 t0 = Tp[0], t1 = Tp[1], t2 = Tp[2], t3 = Tp[3];
        a0.x = fmaf(wc, t0.x, a0.x); a0.y = fmaf(wc, t0.y, a0.y);
        a0.z = fmaf(wc, t0.z, a0.z); a0.w = fmaf(wc, t0.w, a0.w);
        a1.x = fmaf(wc, t1.x, a1.x); a1.y = fmaf(wc, t1.y, a1.y);
        a1.z = fmaf(wc, t1.z, a1.z); a1.w = fmaf(wc, t1.w, a1.w);
        a2.x = fmaf(wc, t2.x, a2.x); a2.y = fmaf(wc, t2.y, a2.y);
        a2.z = fmaf(wc, t2.z, a2.z); a2.w = fmaf(wc, t2.w, a2.w);
        a3.x = fmaf(wc, t3.x, a3.x); a3.y = fmaf(wc, t3.y, a3.y);
        a3.z = fmaf(wc, t3.z, a3.z); a3.w = fmaf(wc, t3.w, a3.w);
    }

    float4* op = reinterpret_cast<float4*>(out + (size_t)l*OW_STRIDE) + (((b*NN + j)*NN + k)<<2);
    op[0]=a0; op[1]=a1; op[2]=a2; op[3]=a3;
}

// ---------------- launch ----------------
extern "C" void kernel_launch(void* const* d_in, const int* in_sizes, int n_in,
                              void* d_out, int out_size){
    (void)n_in; (void)out_size;
    // Inputs are in setup_inputs() dict order: w0,b0,w1,b1,w2,b2,w3,b3,s_*...
    // Detect w vs b by element count to be robust to ordering.
    const float* w[4]; const float* bb[4];
    int wi = 0, bi = 0;
    for (int i = 0; i < 8; i++){
        if (in_sizes[i] > 1000000) w[wi++] = (const float*)d_in[i];
        else                       bb[bi++] = (const float*)d_in[i];
    }
    const float* sw0 = (const float*)d_in[8];
    const float* sb0 = (const float*)d_in[9];
    const float* sw1 = (const float*)d_in[10];
    const float* sb1 = (const float*)d_in[11];
    const float* sw2 = (const float*)d_in[12];
    const float* sb2 = (const float*)d_in[13];
    const float* swo = (const float*)d_in[14];
    const float* sbo = (const float*)d_in[15];
    float* out = (float*)d_out;

    zero_kernel<<<512, 256>>>();
    siren_kernel<<<100, NHID>>>(sw0, sb0, sw1, sb1, sw2, sb2, swo, sbo);
    reduce_kernel<<<dim3(16, NB, NL), 256>>>(w[0], w[1], w[2], w[3]);
    sumsb_kernel<<<64, 256>>>(bb[0], bb[1], bb[2], bb[3]);
    base_kernel<<<1, 1024>>>();
    colrow_kernel<<<3072, 256>>>(bb[0], bb[1], bb[2], bb[3], out);
    main_kernel<<<dim3(NN, NB, NL), 256>>>(w[0], w[1], w[2], w[3], out);
}

// round 3
// speedup vs baseline: 1.0880x; 1.0880x over previous
#include <cuda_runtime.h>
#include <math.h>

#define NL 4
#define NB 16
#define NN 256
#define NC 16
#define NHID 64
#define INV256F (1.0f/256.0f)
#define INVNORM 0.06454972243679028f   /* 1/sqrt(240) */
#define OW_STRIDE 16842752             /* per-layer stride in d_out (ow + ob) */
#define OB_OFF    16777216             /* offset of ob within a layer chunk */

// ---------------- scratch (device globals; no allocs) ----------------
__device__ float g_terms[100*256];          // 100 siren points x (16c x 16d)
__device__ float g_rsums[NL*NB*NN*NC];      // mean over j  -> [l][b][k][c]
__device__ float g_csums[NL*NB*NN*NC];      // mean over k  -> [l][b][j][c]
__device__ float g_rpart[16*NL*NB*NN*NC];   // 16 j-tile partial sums of w over j
__device__ float g_allsums[NB*NC*NL];       // [b][c][l]
__device__ float g_sumsb[NB*NC*NL];         // [b][c][l]
__device__ float g_basew[NL*NB*NC];         // [l][b][d]
__device__ float g_baseb[NL*NB*NC];
__device__ float g_colterm[NL*NB*NN*NC];    // [l][b][j][d] (base folded in)
__device__ float g_rowterm[NL*NB*NN*NC];    // [l][b][k][d]

// g_terms point layout:
// global: t*16 + a*4 + b   (t=0..3)
// diag:   64 + t*4 + i     (t=0..5)
// p1:     88 + t*3 + i     (t=0..1, i=0..2)
// m1:     94 + t*3 + i

__device__ __forceinline__ float f_li(int i){ return -1.0f + (2.0f/3.0f)*i; }
__device__ __forceinline__ float f_ti(int m){ return -1.0f + (2.0f/13.0f)*m; }

// ---------------- SIREN: 100 points -> 256 outputs each ----------------
__global__ void siren_kernel(const float* __restrict__ sw0, const float* __restrict__ sb0,
                             const float* __restrict__ sw1, const float* __restrict__ sb1,
                             const float* __restrict__ sw2, const float* __restrict__ sb2,
                             const float* __restrict__ swo, const float* __restrict__ sbo){
    int p = blockIdx.x;
    int t = threadIdx.x;
    float x0, x1, x2;
    if (p < 64){        int tt=p>>4, a=(p>>2)&3, bb=p&3; x0=f_li(a);   x1=f_li(bb);  x2=f_ti(tt); }
    else if (p < 88){   int q=p-64;  int tt=q>>2, i=q&3; x0=f_li(i);   x1=f_li(i);   x2=f_ti(4+tt); }
    else if (p < 94){   int q=p-88;  int tt=q/3,  i=q%3; x0=f_li(i);   x1=f_li(i+1); x2=f_ti(10+tt); }
    else {              int q=p-94;  int tt=q/3,  i=q%3; x0=f_li(i+1); x1=f_li(i);   x2=f_ti(12+tt); }

    __shared__ float h[NHID];
    float v = x0*sw0[t] + x1*sw0[NHID+t] + x2*sw0[2*NHID+t] + sb0[t];
    h[t] = sinf(30.0f * v);
    __syncthreads();

    float a1 = sb1[t];
    #pragma unroll 8
    for (int j=0;j<NHID;j++) a1 = fmaf(h[j], sw1[j*NHID+t], a1);
    a1 = sinf(a1);
    __syncthreads(); h[t] = a1; __syncthreads();

    float a2 = sb2[t];
    #pragma unroll 8
    for (int j=0;j<NHID;j++) a2 = fmaf(h[j], sw2[j*NHID+t], a2);
    a2 = sinf(a2);
    __syncthreads(); h[t] = a2; __syncthreads();

    for (int o=t; o<256; o+=NHID){
        float acc = sbo[o];
        #pragma unroll 8
        for (int j=0;j<NHID;j++) acc = fmaf(h[j], swo[j*256+o], acc);
        g_terms[p*256 + o] = acc * INVNORM;
    }
}

// ---------------- reduce pass 1: csums (final) + rsums partials ----------------
// grid: x = jt (16 tiles of 16 j), y = b, z = l ; 256 threads
// thread: c4 = t&3, klocal = t>>2 (0..63); kc loop covers all 256 k.
__global__ void __launch_bounds__(256, 2)
reduce_pass1(const float* __restrict__ w0, const float* __restrict__ w1,
             const float* __restrict__ w2, const float* __restrict__ w3){
    int jt = blockIdx.x;
    int b  = blockIdx.y;
    int l  = blockIdx.z;
    const float* w = (l==0)?w0:(l==1)?w1:(l==2)?w2:w3;

    int t      = threadIdx.x;
    int c4     = t & 3;
    int klocal = t >> 2;
    int lane   = t & 31;
    int warp   = t >> 5;
    int j0     = jt * 16;

    const float4* wp = reinterpret_cast<const float4*>(w);

    float4 csum[16];
    #pragma unroll
    for (int jj=0; jj<16; jj++) csum[jj] = make_float4(0.f,0.f,0.f,0.f);

    #pragma unroll
    for (int kc=0; kc<4; kc++){
        int k = kc*64 + klocal;
        float4 racc = make_float4(0.f,0.f,0.f,0.f);
        int base = ((b*NN + j0)*NN + k)*4 + c4;     // float4 index
        #pragma unroll
        for (int jj=0; jj<16; jj++){
            float4 v = __ldg(wp + base + jj*1024);  // j stride = 256*16/4 float4
            racc.x += v.x; racc.y += v.y; racc.z += v.z; racc.w += v.w;
            csum[jj].x += v.x; csum[jj].y += v.y; csum[jj].z += v.z; csum[jj].w += v.w;
        }
        // rsums partial for this j-tile: plain coalesced store
        float4* rp = reinterpret_cast<float4*>(g_rpart) +
                     ((((jt*NL + l)*NB + b)*NN + k)*4 + c4);
        *rp = racc;
    }

    // csums: reduce over the 8 klocal values in each warp (lane bits 2..4)
    __shared__ float4 sh[8][16][4];
    #pragma unroll
    for (int jj=0; jj<16; jj++){
        float4 s = csum[jj];
        #pragma unroll
        for (int m=4; m<32; m<<=1){
            s.x += __shfl_xor_sync(0xffffffffu, s.x, m);
            s.y += __shfl_xor_sync(0xffffffffu, s.y, m);
            s.z += __shfl_xor_sync(0xffffffffu, s.z, m);
            s.w += __shfl_xor_sync(0xffffffffu, s.w, m);
        }
        if (lane < 4) sh[warp][jj][lane] = s;
    }
    __syncthreads();

    if (t < 64){
        int jj = t >> 2, cc = t & 3;
        float4 s = make_float4(0.f,0.f,0.f,0.f);
        #pragma unroll
        for (int ww=0; ww<8; ww++){
            float4 v = sh[ww][jj][cc];
            s.x += v.x; s.y += v.y; s.z += v.z; s.w += v.w;
        }
        s.x *= INV256F; s.y *= INV256F; s.z *= INV256F; s.w *= INV256F;
        reinterpret_cast<float4*>(g_csums)[((l*NB + b)*NN + j0 + jj)*4 + cc] = s;
    }
}

// ---------------- reduce pass 2: rsums (final) + allsums ----------------
// 64 blocks (l*16+b), 256 threads: t = k
__global__ void reduce_pass2(){
    int l = blockIdx.x >> 4, b = blockIdx.x & 15;
    int k = threadIdx.x;
    int lane = k & 31, warp = k >> 5;
    __shared__ float4 sh2[8][4];

    float4 tot[4];
    #pragma unroll
    for (int c4=0; c4<4; c4++){
        float4 s = make_float4(0.f,0.f,0.f,0.f);
        #pragma unroll
        for (int jt=0; jt<16; jt++){
            float4 v = __ldg(reinterpret_cast<const float4*>(g_rpart) +
                             ((((jt*NL + l)*NB + b)*NN + k)*4 + c4));
            s.x += v.x; s.y += v.y; s.z += v.z; s.w += v.w;
        }
        s.x *= INV256F; s.y *= INV256F; s.z *= INV256F; s.w *= INV256F;
        reinterpret_cast<float4*>(g_rsums)[((l*NB + b)*NN + k)*4 + c4] = s;
        tot[c4] = s;
    }
    // allsums: mean over k of rsums
    #pragma unroll
    for (int c4=0; c4<4; c4++){
        float4 s = tot[c4];
        #pragma unroll
        for (int m=1; m<32; m<<=1){
            s.x += __shfl_xor_sync(0xffffffffu, s.x, m);
            s.y += __shfl_xor_sync(0xffffffffu, s.y, m);
            s.z += __shfl_xor_sync(0xffffffffu, s.z, m);
            s.w += __shfl_xor_sync(0xffffffffu, s.w, m);
        }
        if (lane == 0) sh2[warp][c4] = s;
    }
    __syncthreads();
    if (k < 4){
        float4 s = make_float4(0.f,0.f,0.f,0.f);
        #pragma unroll
        for (int ww=0; ww<8; ww++){
            float4 v = sh2[ww][k];
            s.x += v.x; s.y += v.y; s.z += v.z; s.w += v.w;
        }
        int cb = k*4;
        g_allsums[b*64 + (cb+0)*4 + l] = s.x * INV256F;
        g_allsums[b*64 + (cb+1)*4 + l] = s.y * INV256F;
        g_allsums[b*64 + (cb+2)*4 + l] = s.z * INV256F;
        g_allsums[b*64 + (cb+3)*4 + l] = s.w * INV256F;
    }
}

// ---------------- sums_b: [b][c][l] = mean_j b_l[b,j,c] ----------------
__global__ void sumsb_kernel(const float* __restrict__ b0, const float* __restrict__ b1,
                             const float* __restrict__ b2, const float* __restrict__ b3){
    int lb = blockIdx.x;
    int l = lb >> 4, b = lb & 15;
    const float* bl = (l==0)?b0:(l==1)?b1:(l==2)?b2:b3;
    int t = threadIdx.x;
    int c = t & 15, jg = t >> 4;
    float acc = 0.f;
    #pragma unroll 4
    for (int m=0; m<16; m++){
        int j = jg*16 + m;
        acc += __ldg(&bl[(b*NN + j)*NC + c]);
    }
    __shared__ float sh[256];
    sh[t] = acc;
    __syncthreads();
    if (t < 16){
        float s = 0.f;
        #pragma unroll
        for (int g=0; g<16; g++) s += sh[g*16 + t];
        g_sumsb[b*64 + t*4 + l] = s * INV256F;
    }
}

// ---------------- base terms from allsums / sums_b ----------------
__global__ void base_kernel(){
    int id = threadIdx.x;
    int l = id >> 8, b = (id >> 4) & 15, d = id & 15;
    float accw = 0.f, accb = 0.f;
    #pragma unroll
    for (int lp=0; lp<NL; lp++){
        #pragma unroll
        for (int c=0; c<NC; c++){
            float as = g_allsums[b*64 + c*4 + lp];
            float sb = g_sumsb[b*64 + c*4 + lp];
            int e = c*16 + d;
            accw = fmaf(as, g_terms[(     l*4 + lp)*256 + e], accw);
            accw = fmaf(sb, g_terms[(16 + l*4 + lp)*256 + e], accw);
            accb = fmaf(as, g_terms[(32 + l*4 + lp)*256 + e], accb);
            accb = fmaf(sb, g_terms[(48 + l*4 + lp)*256 + e], accb);
        }
    }
    g_basew[id] = accw;
    g_baseb[id] = accb;
}

// ---------------- colterm / rowterm / ob ----------------
__global__ void colrow_kernel(const float* __restrict__ b0, const float* __restrict__ b1,
                              const float* __restrict__ b2, const float* __restrict__ b3,
                              float* __restrict__ out){
    int gid = blockIdx.x*blockDim.x + threadIdx.x;
    int sec = gid >> 18;
    int r   = gid & 262143;
    int l = r >> 16, b = (r >> 12) & 15, x = (r >> 4) & 255, d = r & 15;
    const float* bl = (l==0)?b0:(l==1)?b1:(l==2)?b2:b3;

    if (sec == 0){
        float acc = g_basew[(l*NB + b)*NC + d];
        const float* cs = &g_csums[((l*NB + b)*NN + x)*NC];
        const float* T1 = &g_terms[(68 + l)*256];          // t_w_wcol
        #pragma unroll
        for (int c=0; c<NC; c++) acc = fmaf(cs[c], T1[c*16 + d], acc);
        if (l > 0){
            const float* rs  = &g_rsums[(((l-1)*NB + b)*NN + x)*NC];
            const float* bp  = ((l-1)==0?b0:(l-1)==1?b1:(l-1)==2?b2:b3) + (b*NN + x)*NC;
            const float* Tm0 = &g_terms[(94 + (l-1))*256]; // t_w_wm1
            const float* Tm1 = &g_terms[(97 + (l-1))*256]; // t_w_bm1
            #pragma unroll
            for (int c=0; c<NC; c++){
                acc = fmaf(rs[c], Tm0[c*16 + d], acc);
                acc = fmaf(bp[c], Tm1[c*16 + d], acc);
            }
        }
        g_colterm[r] = acc;
    } else if (sec == 1){
        float acc = 0.f;
        const float* rs = &g_rsums[((l*NB + b)*NN + x)*NC];
        const float* bv = bl + (b*NN + x)*NC;
        const float* T0 = &g_terms[(64 + l)*256];          // t_w_wrow
        const float* T3 = &g_terms[(76 + l)*256];          // t_w_b
        #pragma unroll
        for (int c=0; c<NC; c++){
            acc = fmaf(rs[c], T0[c*16 + d], acc);
            acc = fmaf(bv[c], T3[c*16 + d], acc);
        }
        if (l < 3){
            const float* cs = &g_csums[(((l+1)*NB + b)*NN + x)*NC];
            const float* Tp = &g_terms[(88 + l)*256];      // t_w_wp1
            #pragma unroll
            for (int c=0; c<NC; c++) acc = fmaf(cs[c], Tp[c*16 + d], acc);
        }
        g_rowterm[r] = acc;
    } else {
        float acc = g_baseb[(l*NB + b)*NC + d];
        const float* rs = &g_rsums[((l*NB + b)*NN + x)*NC];
        const float* bv = bl + (b*NN + x)*NC;
        const float* T5 = &g_terms[(84 + l)*256];          // t_bb
        const float* T4 = &g_terms[(80 + l)*256];          // t_b_wcol
        #pragma unroll
        for (int c=0; c<NC; c++){
            acc = fmaf(bv[c], T5[c*16 + d], acc);
            acc = fmaf(rs[c], T4[c*16 + d], acc);
        }
        if (l < 3){
            const float* cs = &g_csums[(((l+1)*NB + b)*NN + x)*NC];
            const float* Tb = &g_terms[(91 + l)*256];      // t_b_wp1
            #pragma unroll
            for (int c=0; c<NC; c++) acc = fmaf(cs[c], Tb[c*16 + d], acc);
        }
        out[(size_t)l*OW_STRIDE + OB_OFF + (b*NN + x)*NC + d] = acc;
    }
}

// ---------------- main output pass: ow = w@T + colterm + rowterm ----------------
__global__ void __launch_bounds__(256)
main_kernel(const float* __restrict__ w0, const float* __restrict__ w1,
            const float* __restrict__ w2, const float* __restrict__ w3,
            float* __restrict__ out){
    int l = 3 - blockIdx.z;
    int b = blockIdx.y;
    int j = blockIdx.x;
    int t = threadIdx.x;
    const float* w = (l==0)?w0:(l==1)?w1:(l==2)?w2:w3;

    __shared__ float shT[256];
    __shared__ float shcol[16];
    shT[t] = __ldg(&g_terms[(72 + l)*256 + t]);            // t_w_w[l]
    if (t < 16) shcol[t] = g_colterm[((l*NB + b)*NN + j)*NC + t];
    __syncthreads();

    int k = t;
    const float4* wp = reinterpret_cast<const float4*>(w) + (((b*NN + j)*NN + k)<<2);
    float4 wv0 = __ldg(wp+0), wv1 = __ldg(wp+1), wv2 = __ldg(wp+2), wv3 = __ldg(wp+3);
    float wr[16];
    wr[0]=wv0.x; wr[1]=wv0.y; wr[2]=wv0.z; wr[3]=wv0.w;
    wr[4]=wv1.x; wr[5]=wv1.y; wr[6]=wv1.z; wr[7]=wv1.w;
    wr[8]=wv2.x; wr[9]=wv2.y; wr[10]=wv2.z; wr[11]=wv2.w;
    wr[12]=wv3.x; wr[13]=wv3.y; wr[14]=wv3.z; wr[15]=wv3.w;

    const float4* rp = reinterpret_cast<const float4*>(g_rowterm) + (((l*NB + b)*NN + k)<<2);
    float4 a0 = __ldg(rp+0), a1 = __ldg(rp+1), a2 = __ldg(rp+2), a3 = __ldg(rp+3);
    a0.x += shcol[0];  a0.y += shcol[1];  a0.z += shcol[2];  a0.w += shcol[3];
    a1.x += shcol[4];  a1.y += shcol[5];  a1.z += shcol[6];  a1.w += shcol[7];
    a2.x += shcol[8];  a2.y += shcol[9];  a2.z += shcol[10]; a2.w += shcol[11];
    a3.x += shcol[12]; a3.y += shcol[13]; a3.z += shcol[14]; a3.w += shcol[15];

    #pragma unroll
    for (int c=0; c<16; c++){
        float wc = wr[c];
        const float4* Tp = reinterpret_cast<const float4*>(&shT[c*16]);
        float4 t0 = Tp[0], t1 = Tp[1], t2 = Tp[2], t3 = Tp[3];
        a0.x = fmaf(wc, t0.x, a0.x); a0.y = fmaf(wc, t0.y, a0.y);
        a0.z = fmaf(wc, t0.z, a0.z); a0.w = fmaf(wc, t0.w, a0.w);
        a1.x = fmaf(wc, t1.x, a1.x); a1.y = fmaf(wc, t1.y, a1.y);
        a1.z = fmaf(wc, t1.z, a1.z); a1.w = fmaf(wc, t1.w, a1.w);
        a2.x = fmaf(wc, t2.x, a2.x); a2.y = fmaf(wc, t2.y, a2.y);
        a2.z = fmaf(wc, t2.z, a2.z); a2.w = fmaf(wc, t2.w, a2.w);
        a3.x = fmaf(wc, t3.x, a3.x); a3.y = fmaf(wc, t3.y, a3.y);
        a3.z = fmaf(wc, t3.z, a3.z); a3.w = fmaf(wc, t3.w, a3.w);
    }

    float4* op = reinterpret_cast<float4*>(out + (size_t)l*OW_STRIDE) + (((b*NN + j)*NN + k)<<2);
    op[0]=a0; op[1]=a1; op[2]=a2; op[3]=a3;
}

// ---------------- launch ----------------
extern "C" void kernel_launch(void* const* d_in, const int* in_sizes, int n_in,
                              void* d_out, int out_size){
    (void)n_in; (void)out_size;
    // Inputs in setup_inputs() dict order: w0,b0,w1,b1,... — detect by size.
    const float* w[4]; const float* bb[4];
    int wi = 0, bi = 0;
    for (int i = 0; i < 8; i++){
        if (in_sizes[i] > 1000000) w[wi++] = (const float*)d_in[i];
        else                       bb[bi++] = (const float*)d_in[i];
    }
    const float* sw0 = (const float*)d_in[8];
    const float* sb0 = (const float*)d_in[9];
    const float* sw1 = (const float*)d_in[10];
    const float* sb1 = (const float*)d_in[11];
    const float* sw2 = (const float*)d_in[12];
    const float* sb2 = (const float*)d_in[13];
    const float* swo = (const float*)d_in[14];
    const float* sbo = (const float*)d_in[15];
    float* out = (float*)d_out;

    siren_kernel<<<100, NHID>>>(sw0, sb0, sw1, sb1, sw2, sb2, swo, sbo);
    reduce_pass1<<<dim3(16, NB, NL), 256>>>(w[0], w[1], w[2], w[3]);
    reduce_pass2<<<64, 256>>>();
    sumsb_kernel<<<64, 256>>>(bb[0], bb[1], bb[2], bb[3]);
    base_kernel<<<1, 1024>>>();
    colrow_kernel<<<3072, 256>>>(bb[0], bb[1], bb[2], bb[3], out);
    main_kernel<<<dim3(NN, NB, NL), 256>>>(w[0], w[1], w[2], w[3], out);
}

// round 4
// speedup vs baseline: 1.1321x; 1.0406x over previous
#include <cuda_runtime.h>
#include <math.h>

#define NL 4
#define NB 16
#define NN 256
#define NC 16
#define NHID 64
#define INV256F (1.0f/256.0f)
#define INVNORM 0.06454972243679028f   /* 1/sqrt(240) */
#define OW_STRIDE 16842752             /* per-layer stride in d_out (ow + ob) */
#define OB_OFF    16777216             /* offset of ob within a layer chunk */

// ---------------- scratch (device globals; no allocs) ----------------
__device__ float g_terms[100*256];          // 100 siren points x (16c x 16d)
__device__ float g_rsums[NL*NB*NN*NC];      // mean over j  -> [l][b][k][c]
__device__ float g_csums[NL*NB*NN*NC];      // mean over k  -> [l][b][j][c]
__device__ float g_rpart[16*NL*NB*NN*NC];   // 16 j-tile partial sums of w over j
__device__ float g_allsums[NB*NC*NL];       // [b][c][l]
__device__ float g_sumsb[NB*NC*NL];         // [b][c][l]
__device__ float g_basew[NL*NB*NC];         // [l][b][d]
__device__ float g_baseb[NL*NB*NC];
__device__ float g_colterm[NL*NB*NN*NC];    // [l][b][j][d] (base folded in)
__device__ float g_rowterm[NL*NB*NN*NC];    // [l][b][k][d]

// g_terms point layout:
// global: t*16 + a*4 + b   (t=0..3)
// diag:   64 + t*4 + i     (t=0..5)
// p1:     88 + t*3 + i     (t=0..1, i=0..2)
// m1:     94 + t*3 + i

__device__ __forceinline__ float f_li(int i){ return -1.0f + (2.0f/3.0f)*i; }
__device__ __forceinline__ float f_ti(int m){ return -1.0f + (2.0f/13.0f)*m; }

__device__ __forceinline__ unsigned long long pack2(float lo, float hi){
    unsigned long long r;
    asm("mov.b64 %0, {%1, %2};" : "=l"(r) : "f"(lo), "f"(hi));
    return r;
}
__device__ __forceinline__ unsigned long long bcast2(float v){
    unsigned long long r;
    asm("mov.b64 %0, {%1, %1};" : "=l"(r) : "f"(v));
    return r;
}
__device__ __forceinline__ void fma2(unsigned long long& d, unsigned long long a, unsigned long long b){
    asm("fma.rn.f32x2 %0, %1, %2, %0;" : "+l"(d) : "l"(a), "l"(b));
}
__device__ __forceinline__ unsigned long long add2(unsigned long long a, unsigned long long b){
    unsigned long long r;
    asm("add.rn.f32x2 %0, %1, %2;" : "=l"(r) : "l"(a), "l"(b));
    return r;
}
__device__ __forceinline__ void unpack2(unsigned long long v, float& lo, float& hi){
    asm("mov.b64 {%0, %1}, %2;" : "=f"(lo), "=f"(hi) : "l"(v));
}

// ---------------- SIREN: 100 points -> 256 outputs each ----------------
__global__ void siren_kernel(const float* __restrict__ sw0, const float* __restrict__ sb0,
                             const float* __restrict__ sw1, const float* __restrict__ sb1,
                             const float* __restrict__ sw2, const float* __restrict__ sb2,
                             const float* __restrict__ swo, const float* __restrict__ sbo){
    int p = blockIdx.x;
    int t = threadIdx.x;
    float x0, x1, x2;
    if (p < 64){        int tt=p>>4, a=(p>>2)&3, bb=p&3; x0=f_li(a);   x1=f_li(bb);  x2=f_ti(tt); }
    else if (p < 88){   int q=p-64;  int tt=q>>2, i=q&3; x0=f_li(i);   x1=f_li(i);   x2=f_ti(4+tt); }
    else if (p < 94){   int q=p-88;  int tt=q/3,  i=q%3; x0=f_li(i);   x1=f_li(i+1); x2=f_ti(10+tt); }
    else {              int q=p-94;  int tt=q/3,  i=q%3; x0=f_li(i+1); x1=f_li(i);   x2=f_ti(12+tt); }

    __shared__ float h[NHID];
    float v = x0*sw0[t] + x1*sw0[NHID+t] + x2*sw0[2*NHID+t] + sb0[t];
    h[t] = sinf(30.0f * v);
    __syncthreads();

    float a1 = sb1[t];
    #pragma unroll 8
    for (int j=0;j<NHID;j++) a1 = fmaf(h[j], sw1[j*NHID+t], a1);
    a1 = sinf(a1);
    __syncthreads(); h[t] = a1; __syncthreads();

    float a2 = sb2[t];
    #pragma unroll 8
    for (int j=0;j<NHID;j++) a2 = fmaf(h[j], sw2[j*NHID+t], a2);
    a2 = sinf(a2);
    __syncthreads(); h[t] = a2; __syncthreads();

    for (int o=t; o<256; o+=NHID){
        float acc = sbo[o];
        #pragma unroll 8
        for (int j=0;j<NHID;j++) acc = fmaf(h[j], swo[j*256+o], acc);
        g_terms[p*256 + o] = acc * INVNORM;
    }
}

// ---------------- reduce pass 1: csums (final) + rsums partials ----------------
__global__ void __launch_bounds__(256, 2)
reduce_pass1(const float* __restrict__ w0, const float* __restrict__ w1,
             const float* __restrict__ w2, const float* __restrict__ w3){
    int jt = blockIdx.x;
    int b  = blockIdx.y;
    int l  = blockIdx.z;
    const float* w = (l==0)?w0:(l==1)?w1:(l==2)?w2:w3;

    int t      = threadIdx.x;
    int c4     = t & 3;
    int klocal = t >> 2;
    int lane   = t & 31;
    int warp   = t >> 5;
    int j0     = jt * 16;

    const float4* wp = reinterpret_cast<const float4*>(w);

    float4 csum[16];
    #pragma unroll
    for (int jj=0; jj<16; jj++) csum[jj] = make_float4(0.f,0.f,0.f,0.f);

    #pragma unroll
    for (int kc=0; kc<4; kc++){
        int k = kc*64 + klocal;
        float4 racc = make_float4(0.f,0.f,0.f,0.f);
        int base = ((b*NN + j0)*NN + k)*4 + c4;     // float4 index
        #pragma unroll
        for (int jj=0; jj<16; jj++){
            float4 v = __ldg(wp + base + jj*1024);  // j stride = 1024 float4
            racc.x += v.x; racc.y += v.y; racc.z += v.z; racc.w += v.w;
            csum[jj].x += v.x; csum[jj].y += v.y; csum[jj].z += v.z; csum[jj].w += v.w;
        }
        float4* rp = reinterpret_cast<float4*>(g_rpart) +
                     ((((jt*NL + l)*NB + b)*NN + k)*4 + c4);
        *rp = racc;
    }

    __shared__ float4 sh[8][16][4];
    #pragma unroll
    for (int jj=0; jj<16; jj++){
        float4 s = csum[jj];
        #pragma unroll
        for (int m=4; m<32; m<<=1){
            s.x += __shfl_xor_sync(0xffffffffu, s.x, m);
            s.y += __shfl_xor_sync(0xffffffffu, s.y, m);
            s.z += __shfl_xor_sync(0xffffffffu, s.z, m);
            s.w += __shfl_xor_sync(0xffffffffu, s.w, m);
        }
        if (lane < 4) sh[warp][jj][lane] = s;
    }
    __syncthreads();

    if (t < 64){
        int jj = t >> 2, cc = t & 3;
        float4 s = make_float4(0.f,0.f,0.f,0.f);
        #pragma unroll
        for (int ww=0; ww<8; ww++){
            float4 v = sh[ww][jj][cc];
            s.x += v.x; s.y += v.y; s.z += v.z; s.w += v.w;
        }
        s.x *= INV256F; s.y *= INV256F; s.z *= INV256F; s.w *= INV256F;
        reinterpret_cast<float4*>(g_csums)[((l*NB + b)*NN + j0 + jj)*4 + cc] = s;
    }
}

// ---------------- reduce pass 2: rsums (final) + allsums ----------------
__global__ void reduce_pass2(){
    int l = blockIdx.x >> 4, b = blockIdx.x & 15;
    int k = threadIdx.x;
    int lane = k & 31, warp = k >> 5;
    __shared__ float4 sh2[8][4];

    float4 tot[4];
    #pragma unroll
    for (int c4=0; c4<4; c4++){
        float4 s = make_float4(0.f,0.f,0.f,0.f);
        #pragma unroll
        for (int jt=0; jt<16; jt++){
            float4 v = __ldg(reinterpret_cast<const float4*>(g_rpart) +
                             ((((jt*NL + l)*NB + b)*NN + k)*4 + c4));
            s.x += v.x; s.y += v.y; s.z += v.z; s.w += v.w;
        }
        s.x *= INV256F; s.y *= INV256F; s.z *= INV256F; s.w *= INV256F;
        reinterpret_cast<float4*>(g_rsums)[((l*NB + b)*NN + k)*4 + c4] = s;
        tot[c4] = s;
    }
    #pragma unroll
    for (int c4=0; c4<4; c4++){
        float4 s = tot[c4];
        #pragma unroll
        for (int m=1; m<32; m<<=1){
            s.x += __shfl_xor_sync(0xffffffffu, s.x, m);
            s.y += __shfl_xor_sync(0xffffffffu, s.y, m);
            s.z += __shfl_xor_sync(0xffffffffu, s.z, m);
            s.w += __shfl_xor_sync(0xffffffffu, s.w, m);
        }
        if (lane == 0) sh2[warp][c4] = s;
    }
    __syncthreads();
    if (k < 4){
        float4 s = make_float4(0.f,0.f,0.f,0.f);
        #pragma unroll
        for (int ww=0; ww<8; ww++){
            float4 v = sh2[ww][k];
            s.x += v.x; s.y += v.y; s.z += v.z; s.w += v.w;
        }
        int cb = k*4;
        g_allsums[b*64 + (cb+0)*4 + l] = s.x * INV256F;
        g_allsums[b*64 + (cb+1)*4 + l] = s.y * INV256F;
        g_allsums[b*64 + (cb+2)*4 + l] = s.z * INV256F;
        g_allsums[b*64 + (cb+3)*4 + l] = s.w * INV256F;
    }
}

// ---------------- sums_b ----------------
__global__ void sumsb_kernel(const float* __restrict__ b0, const float* __restrict__ b1,
                             const float* __restrict__ b2, const float* __restrict__ b3){
    int lb = blockIdx.x;
    int l = lb >> 4, b = lb & 15;
    const float* bl = (l==0)?b0:(l==1)?b1:(l==2)?b2:b3;
    int t = threadIdx.x;
    int c = t & 15, jg = t >> 4;
    float acc = 0.f;
    #pragma unroll 4
    for (int m=0; m<16; m++){
        int j = jg*16 + m;
        acc += __ldg(&bl[(b*NN + j)*NC + c]);
    }
    __shared__ float sh[256];
    sh[t] = acc;
    __syncthreads();
    if (t < 16){
        float s = 0.f;
        #pragma unroll
        for (int g=0; g<16; g++) s += sh[g*16 + t];
        g_sumsb[b*64 + t*4 + l] = s * INV256F;
    }
}

// ---------------- base terms ----------------
__global__ void base_kernel(){
    int id = threadIdx.x;
    int l = id >> 8, b = (id >> 4) & 15, d = id & 15;
    float accw = 0.f, accb = 0.f;
    #pragma unroll
    for (int lp=0; lp<NL; lp++){
        #pragma unroll
        for (int c=0; c<NC; c++){
            float as = g_allsums[b*64 + c*4 + lp];
            float sb = g_sumsb[b*64 + c*4 + lp];
            int e = c*16 + d;
            accw = fmaf(as, g_terms[(     l*4 + lp)*256 + e], accw);
            accw = fmaf(sb, g_terms[(16 + l*4 + lp)*256 + e], accw);
            accb = fmaf(as, g_terms[(32 + l*4 + lp)*256 + e], accb);
            accb = fmaf(sb, g_terms[(48 + l*4 + lp)*256 + e], accb);
        }
    }
    g_basew[id] = accw;
    g_baseb[id] = accb;
}

// ---------------- colterm / rowterm / ob ----------------
__global__ void colrow_kernel(const float* __restrict__ b0, const float* __restrict__ b1,
                              const float* __restrict__ b2, const float* __restrict__ b3,
                              float* __restrict__ out){
    int gid = blockIdx.x*blockDim.x + threadIdx.x;
    int sec = gid >> 18;
    int r   = gid & 262143;
    int l = r >> 16, b = (r >> 12) & 15, x = (r >> 4) & 255, d = r & 15;
    const float* bl = (l==0)?b0:(l==1)?b1:(l==2)?b2:b3;

    if (sec == 0){
        float acc = g_basew[(l*NB + b)*NC + d];
        const float* cs = &g_csums[((l*NB + b)*NN + x)*NC];
        const float* T1 = &g_terms[(68 + l)*256];          // t_w_wcol
        #pragma unroll
        for (int c=0; c<NC; c++) acc = fmaf(cs[c], T1[c*16 + d], acc);
        if (l > 0){
            const float* rs  = &g_rsums[(((l-1)*NB + b)*NN + x)*NC];
            const float* bp  = ((l-1)==0?b0:(l-1)==1?b1:(l-1)==2?b2:b3) + (b*NN + x)*NC;
            const float* Tm0 = &g_terms[(94 + (l-1))*256]; // t_w_wm1
            const float* Tm1 = &g_terms[(97 + (l-1))*256]; // t_w_bm1
            #pragma unroll
            for (int c=0; c<NC; c++){
                acc = fmaf(rs[c], Tm0[c*16 + d], acc);
                acc = fmaf(bp[c], Tm1[c*16 + d], acc);
            }
        }
        g_colterm[r] = acc;
    } else if (sec == 1){
        float acc = 0.f;
        const float* rs = &g_rsums[((l*NB + b)*NN + x)*NC];
        const float* bv = bl + (b*NN + x)*NC;
        const float* T0 = &g_terms[(64 + l)*256];          // t_w_wrow
        const float* T3 = &g_terms[(76 + l)*256];          // t_w_b
        #pragma unroll
        for (int c=0; c<NC; c++){
            acc = fmaf(rs[c], T0[c*16 + d], acc);
            acc = fmaf(bv[c], T3[c*16 + d], acc);
        }
        if (l < 3){
            const float* cs = &g_csums[(((l+1)*NB + b)*NN + x)*NC];
            const float* Tp = &g_terms[(88 + l)*256];      // t_w_wp1
            #pragma unroll
            for (int c=0; c<NC; c++) acc = fmaf(cs[c], Tp[c*16 + d], acc);
        }
        g_rowterm[r] = acc;
    } else {
        float acc = g_baseb[(l*NB + b)*NC + d];
        const float* rs = &g_rsums[((l*NB + b)*NN + x)*NC];
        const float* bv = bl + (b*NN + x)*NC;
        const float* T5 = &g_terms[(84 + l)*256];          // t_bb
        const float* T4 = &g_terms[(80 + l)*256];          // t_b_wcol
        #pragma unroll
        for (int c=0; c<NC; c++){
            acc = fmaf(bv[c], T5[c*16 + d], acc);
            acc = fmaf(rs[c], T4[c*16 + d], acc);
        }
        if (l < 3){
            const float* cs = &g_csums[(((l+1)*NB + b)*NN + x)*NC];
            const float* Tb = &g_terms[(91 + l)*256];      // t_b_wp1
            #pragma unroll
            for (int c=0; c<NC; c++) acc = fmaf(cs[c], Tb[c*16 + d], acc);
        }
        out[(size_t)l*OW_STRIDE + OB_OFF + (b*NN + x)*NC + d] = acc;
    }
}

// ---------------- main output pass (quad-split, fully coalesced) ----------------
// grid (j=256, b=16, l=4), 256 threads. thread t = (k8 = t>>2, q = t&3).
// kc loop x4 covers k = kc*64 + k8. Each thread handles c-quarter q of its row,
// computes partials for all 16 d (f32x2), then 2-round quad butterfly leaves it
// owning d-quarter q. All global accesses: consecutive float4 per consecutive t.
__global__ void __launch_bounds__(256)
main_kernel(const float* __restrict__ w0, const float* __restrict__ w1,
            const float* __restrict__ w2, const float* __restrict__ w3,
            float* __restrict__ out){
    int l = 3 - blockIdx.z;
    int b = blockIdx.y;
    int j = blockIdx.x;
    int t = threadIdx.x;
    int q = t & 3;
    const float* w = (l==0)?w0:(l==1)?w1:(l==2)?w2:w3;

    __shared__ float T_s[16*20];     // T[c][d], row stride 20 floats
    __shared__ float shcol[16];
    if (t < 64){
        int c = t >> 2, dq = t & 3;
        float4 v = __ldg(reinterpret_cast<const float4*>(g_terms) + (72+l)*64 + t);
        *reinterpret_cast<float4*>(&T_s[c*20 + dq*4]) = v;
    }
    if (t >= 64 && t < 80) shcol[t-64] = g_colterm[((l*NB + b)*NN + j)*NC + (t-64)];
    __syncthreads();

    const float4* wrow = reinterpret_cast<const float4*>(w) + (size_t)(b*NN + j)*1024;
    const float4* rrow = reinterpret_cast<const float4*>(g_rowterm) + (size_t)(l*NB + b)*1024;
    float4*       orow = reinterpret_cast<float4*>(out + (size_t)l*OW_STRIDE) + (size_t)(b*NN + j)*1024;
    float4 colv = *reinterpret_cast<const float4*>(&shcol[q*4]);
    int g = q >> 1, h = q & 1;

    #pragma unroll
    for (int kc=0; kc<4; kc++){
        float4 wv = __ldg(wrow + kc*256 + t);

        unsigned long long p2[8];
        #pragma unroll
        for (int i=0;i<8;i++) p2[i] = 0ull;

        #pragma unroll
        for (int cc=0; cc<4; cc++){
            float wc = (cc==0)?wv.x:(cc==1)?wv.y:(cc==2)?wv.z:wv.w;
            unsigned long long wp = bcast2(wc);
            // c = q*4 + cc ; row base word = c*20
            const ulonglong2* Trow = reinterpret_cast<const ulonglong2*>(&T_s[(q*4+cc)*20]);
            #pragma unroll
            for (int dq=0; dq<4; dq++){
                ulonglong2 tv = Trow[dq];
                fma2(p2[dq*2+0], wp, tv.x);
                fma2(p2[dq*2+1], wp, tv.y);
            }
        }

        // round 1 (xor 2): keep my d-half (g), exchange the other
        #pragma unroll
        for (int m=0; m<4; m++){
            unsigned long long keep = g ? p2[m+4] : p2[m];
            unsigned long long send = g ? p2[m]   : p2[m+4];
            unsigned long long recv = __shfl_xor_sync(0xffffffffu, send, 2);
            p2[m] = add2(keep, recv);
        }
        // round 2 (xor 1): keep my d-quarter (h) within the half
        #pragma unroll
        for (int m=0; m<2; m++){
            unsigned long long keep = h ? p2[m+2] : p2[m];
            unsigned long long send = h ? p2[m]   : p2[m+2];
            unsigned long long recv = __shfl_xor_sync(0xffffffffu, send, 1);
            p2[m] = add2(keep, recv);
        }

        float4 res;
        unpack2(p2[0], res.x, res.y);
        unpack2(p2[1], res.z, res.w);
        float4 rv = __ldg(rrow + kc*256 + t);
        res.x += colv.x + rv.x;
        res.y += colv.y + rv.y;
        res.z += colv.z + rv.z;
        res.w += colv.w + rv.w;
        orow[kc*256 + t] = res;
    }
}

// ---------------- launch ----------------
extern "C" void kernel_launch(void* const* d_in, const int* in_sizes, int n_in,
                              void* d_out, int out_size){
    (void)n_in; (void)out_size;
    const float* w[4]; const float* bb[4];
    int wi = 0, bi = 0;
    for (int i = 0; i < 8; i++){
        if (in_sizes[i] > 1000000) w[wi++] = (const float*)d_in[i];
        else                       bb[bi++] = (const float*)d_in[i];
    }
    const float* sw0 = (const float*)d_in[8];
    const float* sb0 = (const float*)d_in[9];
    const float* sw1 = (const float*)d_in[10];
    const float* sb1 = (const float*)d_in[11];
    const float* sw2 = (const float*)d_in[12];
    const float* sb2 = (const float*)d_in[13];
    const float* swo = (const float*)d_in[14];
    const float* sbo = (const float*)d_in[15];
    float* out = (float*)d_out;

    siren_kernel<<<100, NHID>>>(sw0, sb0, sw1, sb1, sw2, sb2, swo, sbo);
    reduce_pass1<<<dim3(16, NB, NL), 256>>>(w[0], w[1], w[2], w[3]);
    reduce_pass2<<<64, 256>>>();
    sumsb_kernel<<<64, 256>>>(bb[0], bb[1], bb[2], bb[3]);
    base_kernel<<<1, 1024>>>();
    colrow_kernel<<<3072, 256>>>(bb[0], bb[1], bb[2], bb[3], out);
    main_kernel<<<dim3(NN, NB, NL), 256>>>(w[0], w[1], w[2], w[3], out);
}

// round 6
// speedup vs baseline: 1.2169x; 1.0749x over previous
#include <cuda_runtime.h>
#include <math.h>

#define NL 4
#define NB 16
#define NN 256
#define NC 16
#define NHID 64
#define INV256F (1.0f/256.0f)
#define INVNORM 0.06454972243679028f   /* 1/sqrt(240) */
#define OW_STRIDE 16842752             /* per-layer stride in d_out (ow + ob) */
#define OB_OFF    16777216             /* offset of ob within a layer chunk */

// ---------------- scratch (device globals; no allocs) ----------------
__device__ float g_terms[100*256];          // 100 siren points x (16c x 16d)
__device__ float g_rsums[NL*NB*NN*NC];      // mean over j  -> [l][b][k][c]
__device__ float g_csums[NL*NB*NN*NC];      // mean over k  -> [l][b][j][c]
__device__ float g_rpart[4*NL*NB*NN*NC];    // 4 j-quarter partial sums of w over j
__device__ float g_allsums[NB*NC*NL];       // [b][c][l]
__device__ float g_sumsb[NB*NC*NL];         // [b][c][l]
__device__ float g_basew[NL*NB*NC];         // [l][b][d]
__device__ float g_baseb[NL*NB*NC];
__device__ float g_colterm[NL*NB*NN*NC];    // [l][b][j][d] (base folded in)
__device__ float g_rowterm[NL*NB*NN*NC];    // [l][b][k][d]

// g_terms point layout:
// global: t*16 + a*4 + b   (t=0..3)
// diag:   64 + t*4 + i     (t=0..5)
// p1:     88 + t*3 + i     (t=0..1, i=0..2)
// m1:     94 + t*3 + i

__device__ __forceinline__ float f_li(int i){ return -1.0f + (2.0f/3.0f)*i; }
__device__ __forceinline__ float f_ti(int m){ return -1.0f + (2.0f/13.0f)*m; }

__device__ __forceinline__ unsigned long long pack2(float lo, float hi){
    unsigned long long r;
    asm("mov.b64 %0, {%1, %2};" : "=l"(r) : "f"(lo), "f"(hi));
    return r;
}
__device__ __forceinline__ void fma2(unsigned long long& d, unsigned long long a, unsigned long long b){
    asm("fma.rn.f32x2 %0, %1, %2, %0;" : "+l"(d) : "l"(a), "l"(b));
}
__device__ __forceinline__ void unpack2(unsigned long long v, float& lo, float& hi){
    asm("mov.b64 {%0, %1}, %2;" : "=f"(lo), "=f"(hi) : "l"(v));
}

// ---------------- SIREN: 100 points -> 256 outputs each ----------------
__global__ void siren_kernel(const float* __restrict__ sw0, const float* __restrict__ sb0,
                             const float* __restrict__ sw1, const float* __restrict__ sb1,
                             const float* __restrict__ sw2, const float* __restrict__ sb2,
                             const float* __restrict__ swo, const float* __restrict__ sbo){
    int p = blockIdx.x;
    int t = threadIdx.x;
    float x0, x1, x2;
    if (p < 64){        int tt=p>>4, a=(p>>2)&3, bb=p&3; x0=f_li(a);   x1=f_li(bb);  x2=f_ti(tt); }
    else if (p < 88){   int q=p-64;  int tt=q>>2, i=q&3; x0=f_li(i);   x1=f_li(i);   x2=f_ti(4+tt); }
    else if (p < 94){   int q=p-88;  int tt=q/3,  i=q%3; x0=f_li(i);   x1=f_li(i+1); x2=f_ti(10+tt); }
    else {              int q=p-94;  int tt=q/3,  i=q%3; x0=f_li(i+1); x1=f_li(i);   x2=f_ti(12+tt); }

    __shared__ float h[NHID];
    float v = x0*sw0[t] + x1*sw0[NHID+t] + x2*sw0[2*NHID+t] + sb0[t];
    h[t] = sinf(30.0f * v);
    __syncthreads();

    float a1 = sb1[t];
    #pragma unroll 8
    for (int j=0;j<NHID;j++) a1 = fmaf(h[j], sw1[j*NHID+t], a1);
    a1 = sinf(a1);
    __syncthreads(); h[t] = a1; __syncthreads();

    float a2 = sb2[t];
    #pragma unroll 8
    for (int j=0;j<NHID;j++) a2 = fmaf(h[j], sw2[j*NHID+t], a2);
    a2 = sinf(a2);
    __syncthreads(); h[t] = a2; __syncthreads();

    for (int o=t; o<256; o+=NHID){
        float acc = sbo[o];
        #pragma unroll 8
        for (int j=0;j<NHID;j++) acc = fmaf(h[j], swo[j*256+o], acc);
        g_terms[p*256 + o] = acc * INVNORM;
    }
}

// ---------------- reduce pass 1: csums (final) + rsums partials ----------------
// grid: x = jq (4 quarters of 64 j), y = b, z = l ; 256 threads
// thread: c4 = t&3, klocal = t>>2 (0..63); kc loop covers all 256 k.
// Each block covers 64 j via 4 subtiles of 16; racc[kc] persists across subtiles
// so only 4 rsums partials exist (16.8MB scratch instead of 67MB).
__global__ void __launch_bounds__(256, 2)
reduce_pass1(const float* __restrict__ w0, const float* __restrict__ w1,
             const float* __restrict__ w2, const float* __restrict__ w3){
    int jq = blockIdx.x;
    int b  = blockIdx.y;
    int l  = blockIdx.z;
    const float* w = (l==0)?w0:(l==1)?w1:(l==2)?w2:w3;

    int t      = threadIdx.x;
    int c4     = t & 3;
    int klocal = t >> 2;
    int lane   = t & 31;
    int warp   = t >> 5;

    const float4* wp = reinterpret_cast<const float4*>(w);
    __shared__ float4 sh[8][16][4];

    float4 racc[4];
    #pragma unroll
    for (int kc=0; kc<4; kc++) racc[kc] = make_float4(0.f,0.f,0.f,0.f);

    for (int sub=0; sub<4; sub++){
        int j0 = jq*64 + sub*16;
        float4 csum[16];
        #pragma unroll
        for (int jj=0; jj<16; jj++) csum[jj] = make_float4(0.f,0.f,0.f,0.f);

        #pragma unroll
        for (int kc=0; kc<4; kc++){
            int k = kc*64 + klocal;
            int base = ((b*NN + j0)*NN + k)*4 + c4;     // float4 index
            #pragma unroll
            for (int jj=0; jj<16; jj++){
                float4 v = __ldg(wp + base + jj*1024);  // j stride = 1024 float4
                racc[kc].x += v.x; racc[kc].y += v.y; racc[kc].z += v.z; racc[kc].w += v.w;
                csum[jj].x += v.x; csum[jj].y += v.y; csum[jj].z += v.z; csum[jj].w += v.w;
            }
        }

        // csums: reduce over the 8 klocal values in each warp (lane bits 2..4)
        #pragma unroll
        for (int jj=0; jj<16; jj++){
            float4 s = csum[jj];
            #pragma unroll
            for (int m=4; m<32; m<<=1){
                s.x += __shfl_xor_sync(0xffffffffu, s.x, m);
                s.y += __shfl_xor_sync(0xffffffffu, s.y, m);
                s.z += __shfl_xor_sync(0xffffffffu, s.z, m);
                s.w += __shfl_xor_sync(0xffffffffu, s.w, m);
            }
            if (lane < 4) sh[warp][jj][lane] = s;
        }
        __syncthreads();

        if (t < 64){
            int jj = t >> 2, cc = t & 3;
            float4 s = make_float4(0.f,0.f,0.f,0.f);
            #pragma unroll
            for (int ww=0; ww<8; ww++){
                float4 v = sh[ww][jj][cc];
                s.x += v.x; s.y += v.y; s.z += v.z; s.w += v.w;
            }
            s.x *= INV256F; s.y *= INV256F; s.z *= INV256F; s.w *= INV256F;
            reinterpret_cast<float4*>(g_csums)[((l*NB + b)*NN + j0 + jj)*4 + cc] = s;
        }
        __syncthreads();
    }

    #pragma unroll
    for (int kc=0; kc<4; kc++){
        int k = kc*64 + klocal;
        reinterpret_cast<float4*>(g_rpart)[(((jq*NL + l)*NB + b)*NN + k)*4 + c4] = racc[kc];
    }
}

// ---------------- reduce pass 2: rsums (final) + allsums ----------------
__global__ void reduce_pass2(){
    int l = blockIdx.x >> 4, b = blockIdx.x & 15;
    int k = threadIdx.x;
    int lane = k & 31, warp = k >> 5;
    __shared__ float4 sh2[8][4];

    float4 tot[4];
    #pragma unroll
    for (int c4=0; c4<4; c4++){
        float4 s = make_float4(0.f,0.f,0.f,0.f);
        #pragma unroll
        for (int jq=0; jq<4; jq++){
            float4 v = __ldg(reinterpret_cast<const float4*>(g_rpart) +
                             ((((jq*NL + l)*NB + b)*NN + k)*4 + c4));
            s.x += v.x; s.y += v.y; s.z += v.z; s.w += v.w;
        }
        s.x *= INV256F; s.y *= INV256F; s.z *= INV256F; s.w *= INV256F;
        reinterpret_cast<float4*>(g_rsums)[((l*NB + b)*NN + k)*4 + c4] = s;
        tot[c4] = s;
    }
    #pragma unroll
    for (int c4=0; c4<4; c4++){
        float4 s = tot[c4];
        #pragma unroll
        for (int m=1; m<32; m<<=1){
            s.x += __shfl_xor_sync(0xffffffffu, s.x, m);
            s.y += __shfl_xor_sync(0xffffffffu, s.y, m);
            s.z += __shfl_xor_sync(0xffffffffu, s.z, m);
            s.w += __shfl_xor_sync(0xffffffffu, s.w, m);
        }
        if (lane == 0) sh2[warp][c4] = s;
    }
    __syncthreads();
    if (k < 4){
        float4 s = make_float4(0.f,0.f,0.f,0.f);
        #pragma unroll
        for (int ww=0; ww<8; ww++){
            float4 v = sh2[ww][k];
            s.x += v.x; s.y += v.y; s.z += v.z; s.w += v.w;
        }
        int cb = k*4;
        g_allsums[b*64 + (cb+0)*4 + l] = s.x * INV256F;
        g_allsums[b*64 + (cb+1)*4 + l] = s.y * INV256F;
        g_allsums[b*64 + (cb+2)*4 + l] = s.z * INV256F;
        g_allsums[b*64 + (cb+3)*4 + l] = s.w * INV256F;
    }
}

// ---------------- sums_b ----------------
__global__ void sumsb_kernel(const float* __restrict__ b0, const float* __restrict__ b1,
                             const float* __restrict__ b2, const float* __restrict__ b3){
    int lb = blockIdx.x;
    int l = lb >> 4, b = lb & 15;
    const float* bl = (l==0)?b0:(l==1)?b1:(l==2)?b2:b3;
    int t = threadIdx.x;
    int c = t & 15, jg = t >> 4;
    float acc = 0.f;
    #pragma unroll 4
    for (int m=0; m<16; m++){
        int j = jg*16 + m;
        acc += __ldg(&bl[(b*NN + j)*NC + c]);
    }
    __shared__ float sh[256];
    sh[t] = acc;
    __syncthreads();
    if (t < 16){
        float s = 0.f;
        #pragma unroll
        for (int g=0; g<16; g++) s += sh[g*16 + t];
        g_sumsb[b*64 + t*4 + l] = s * INV256F;
    }
}

// ---------------- base terms ----------------
__global__ void base_kernel(){
    int id = threadIdx.x;
    int l = id >> 8, b = (id >> 4) & 15, d = id & 15;
    float accw = 0.f, accb = 0.f;
    #pragma unroll
    for (int lp=0; lp<NL; lp++){
        #pragma unroll
        for (int c=0; c<NC; c++){
            float as = g_allsums[b*64 + c*4 + lp];
            float sb = g_sumsb[b*64 + c*4 + lp];
            int e = c*16 + d;
            accw = fmaf(as, g_terms[(     l*4 + lp)*256 + e], accw);
            accw = fmaf(sb, g_terms[(16 + l*4 + lp)*256 + e], accw);
            accb = fmaf(as, g_terms[(32 + l*4 + lp)*256 + e], accb);
            accb = fmaf(sb, g_terms[(48 + l*4 + lp)*256 + e], accb);
        }
    }
    g_basew[id] = accw;
    g_baseb[id] = accb;
}

// ---------------- colterm / rowterm / ob ----------------
__global__ void colrow_kernel(const float* __restrict__ b0, const float* __restrict__ b1,
                              const float* __restrict__ b2, const float* __restrict__ b3,
                              float* __restrict__ out){
    int gid = blockIdx.x*blockDim.x + threadIdx.x;
    int sec = gid >> 18;
    int r   = gid & 262143;
    int l = r >> 16, b = (r >> 12) & 15, x = (r >> 4) & 255, d = r & 15;
    const float* bl = (l==0)?b0:(l==1)?b1:(l==2)?b2:b3;

    if (sec == 0){
        float acc = g_basew[(l*NB + b)*NC + d];
        const float* cs = &g_csums[((l*NB + b)*NN + x)*NC];
        const float* T1 = &g_terms[(68 + l)*256];          // t_w_wcol
        #pragma unroll
        for (int c=0; c<NC; c++) acc = fmaf(cs[c], T1[c*16 + d], acc);
        if (l > 0){
            const float* rs  = &g_rsums[(((l-1)*NB + b)*NN + x)*NC];
            const float* bp  = ((l-1)==0?b0:(l-1)==1?b1:(l-1)==2?b2:b3) + (b*NN + x)*NC;
            const float* Tm0 = &g_terms[(94 + (l-1))*256]; // t_w_wm1
            const float* Tm1 = &g_terms[(97 + (l-1))*256]; // t_w_bm1
            #pragma unroll
            for (int c=0; c<NC; c++){
                acc = fmaf(rs[c], Tm0[c*16 + d], acc);
                acc = fmaf(bp[c], Tm1[c*16 + d], acc);
            }
        }
        g_colterm[r] = acc;
    } else if (sec == 1){
        float acc = 0.f;
        const float* rs = &g_rsums[((l*NB + b)*NN + x)*NC];
        const float* bv = bl + (b*NN + x)*NC;
        const float* T0 = &g_terms[(64 + l)*256];          // t_w_wrow
        const float* T3 = &g_terms[(76 + l)*256];          // t_w_b
        #pragma unroll
        for (int c=0; c<NC; c++){
            acc = fmaf(rs[c], T0[c*16 + d], acc);
            acc = fmaf(bv[c], T3[c*16 + d], acc);
        }
        if (l < 3){
            const float* cs = &g_csums[(((l+1)*NB + b)*NN + x)*NC];
            const float* Tp = &g_terms[(88 + l)*256];      // t_w_wp1
            #pragma unroll
            for (int c=0; c<NC; c++) acc = fmaf(cs[c], Tp[c*16 + d], acc);
        }
        g_rowterm[r] = acc;
    } else {
        float acc = g_baseb[(l*NB + b)*NC + d];
        const float* rs = &g_rsums[((l*NB + b)*NN + x)*NC];
        const float* bv = bl + (b*NN + x)*NC;
        const float* T5 = &g_terms[(84 + l)*256];          // t_bb
        const float* T4 = &g_terms[(80 + l)*256];          // t_b_wcol
        #pragma unroll
        for (int c=0; c<NC; c++){
            acc = fmaf(bv[c], T5[c*16 + d], acc);
            acc = fmaf(rs[c], T4[c*16 + d], acc);
        }
        if (l < 3){
            const float* cs = &g_csums[(((l+1)*NB + b)*NN + x)*NC];
            const float* Tb = &g_terms[(91 + l)*256];      // t_b_wp1
            #pragma unroll
            for (int c=0; c<NC; c++) acc = fmaf(cs[c], Tb[c*16 + d], acc);
        }
        out[(size_t)l*OW_STRIDE + OB_OFF + (b*NN + x)*NC + d] = acc;
    }
}

// ---------------- main output pass (register-T, quad gather) ----------------
// grid (j=256, b=16, l=4), 256 threads. thread t = (k = t>>2, q = t&3).
// T transposed into c-paired u64 form Tt[d][c2]; each thread hoists its
// d-quarter (16 LDS.128 once). Per kc: coalesced w load, quad all-gather of
// w c-pairs (6 b64 shfls), 32 FMA2, 4 horizontal adds, coalesced store.
// Zero shared traffic in the hot loop.
__global__ void __launch_bounds__(256, 2)
main_kernel(const float* __restrict__ w0, const float* __restrict__ w1,
            const float* __restrict__ w2, const float* __restrict__ w3,
            float* __restrict__ out){
    int l = 3 - (int)blockIdx.z;
    int b = 15 - (int)blockIdx.y;
    int j = 255 - (int)blockIdx.x;
    int t = threadIdx.x;
    int q = t & 3;
    const float* w = (l==0)?w0:(l==1)?w1:(l==2)?w2:w3;

    __shared__ unsigned long long Tt_s[128];   // [d][c2] c-paired transposed T
    __shared__ float shcol[16];
    if (t < 128){
        int d = t >> 3, c2 = t & 7;
        float lo = __ldg(&g_terms[(72+l)*256 + (2*c2  )*16 + d]);
        float hi = __ldg(&g_terms[(72+l)*256 + (2*c2+1)*16 + d]);
        Tt_s[t] = pack2(lo, hi);
    } else if (t < 144){
        shcol[t-128] = g_colterm[((l*NB + b)*NN + j)*NC + (t-128)];
    }
    __syncthreads();

    // Hoist T rows for my d-quarter, permuted into gather-slot order.
    int q1 = q^1, q2 = q^2, q3 = q^3;
    ulonglong2 TT[4][4];
    #pragma unroll
    for (int dd=0; dd<4; dd++){
        const ulonglong2* row = reinterpret_cast<const ulonglong2*>(&Tt_s[(q*4+dd)*8]);
        TT[dd][0] = row[q];
        TT[dd][1] = row[q1];
        TT[dd][2] = row[q2];
        TT[dd][3] = row[q3];
    }
    float4 colv = *reinterpret_cast<const float4*>(&shcol[q*4]);

    const float4* wrow = reinterpret_cast<const float4*>(w) + (size_t)(b*NN + j)*1024;
    const float4* rrow = reinterpret_cast<const float4*>(g_rowterm) + (size_t)(l*NB + b)*1024;
    float4*       orow = reinterpret_cast<float4*>(out + (size_t)l*OW_STRIDE) + (size_t)(b*NN + j)*1024;

    #pragma unroll
    for (int kc=0; kc<4; kc++){
        float4 wv = __ldg(wrow + kc*256 + t);
        unsigned long long a0 = pack2(wv.x, wv.y);
        unsigned long long a1 = pack2(wv.z, wv.w);
        unsigned long long b0 = __shfl_xor_sync(0xffffffffu, a0, 1);
        unsigned long long b1 = __shfl_xor_sync(0xffffffffu, a1, 1);
        unsigned long long e0 = __shfl_xor_sync(0xffffffffu, a0, 2);
        unsigned long long e1 = __shfl_xor_sync(0xffffffffu, a1, 2);
        unsigned long long f0 = __shfl_xor_sync(0xffffffffu, b0, 2);
        unsigned long long f1 = __shfl_xor_sync(0xffffffffu, b1, 2);

        unsigned long long acc[4] = {0ull, 0ull, 0ull, 0ull};
        #pragma unroll
        for (int dd=0; dd<4; dd++){
            fma2(acc[dd], a0, TT[dd][0].x);
            fma2(acc[dd], a1, TT[dd][0].y);
            fma2(acc[dd], b0, TT[dd][1].x);
            fma2(acc[dd], b1, TT[dd][1].y);
            fma2(acc[dd], e0, TT[dd][2].x);
            fma2(acc[dd], e1, TT[dd][2].y);
            fma2(acc[dd], f0, TT[dd][3].x);
            fma2(acc[dd], f1, TT[dd][3].y);
        }

        float4 rv = __ldg(rrow + kc*256 + t);
        float4 res;
        { float lo, hi; unpack2(acc[0], lo, hi); res.x = lo + hi; }
        { float lo, hi; unpack2(acc[1], lo, hi); res.y = lo + hi; }
        { float lo, hi; unpack2(acc[2], lo, hi); res.z = lo + hi; }
        { float lo, hi; unpack2(acc[3], lo, hi); res.w = lo + hi; }
        res.x += colv.x + rv.x;
        res.y += colv.y + rv.y;
        res.z += colv.z + rv.z;
        res.w += colv.w + rv.w;
        orow[kc*256 + t] = res;
    }
}

// ---------------- launch ----------------
extern "C" void kernel_launch(void* const* d_in, const int* in_sizes, int n_in,
                              void* d_out, int out_size){
    (void)n_in; (void)out_size;
    const float* w[4]; const float* bb[4];
    int wi = 0, bi = 0;
    for (int i = 0; i < 8; i++){
        if (in_sizes[i] > 1000000) w[wi++] = (const float*)d_in[i];
        else                       bb[bi++] = (const float*)d_in[i];
    }
    const float* sw0 = (const float*)d_in[8];
    const float* sb0 = (const float*)d_in[9];
    const float* sw1 = (const float*)d_in[10];
    const float* sb1 = (const float*)d_in[11];
    const float* sw2 = (const float*)d_in[12];
    const float* sb2 = (const float*)d_in[13];
    const float* swo = (const float*)d_in[14];
    const float* sbo = (const float*)d_in[15];
    float* out = (float*)d_out;

    siren_kernel<<<100, NHID>>>(sw0, sb0, sw1, sb1, sw2, sb2, swo, sbo);
    reduce_pass1<<<dim3(4, NB, NL), 256>>>(w[0], w[1], w[2], w[3]);
    reduce_pass2<<<64, 256>>>();
    sumsb_kernel<<<64, 256>>>(bb[0], bb[1], bb[2], bb[3]);
    base_kernel<<<1, 1024>>>();
    colrow_kernel<<<3072, 256>>>(bb[0], bb[1], bb[2], bb[3], out);
    main_kernel<<<dim3(NN, NB, NL), 256>>>(w[0], w[1], w[2], w[3], out);
}